// round 10
// baseline (speedup 1.0000x reference)
#include <cuda_runtime.h>

#define NB   4      // batch
#define CIN  64
#define COUT 32
#define NBANK 4
#define MOD  128
#define DSZ  32
#define EPSV 1e-8f

// -------- scratch (static device globals; no allocation allowed) --------
__device__ float g_w[NB * CIN * 27 * COUT];                 // [b][ci][k][o]  (o contiguous)
__device__ float g_ys[NB * COUT * DSZ * DSZ * DSZ];         // [b][o][z][y][x]  16 MB

// =====================================================================
// Kernel 1: bank select + modulate + demodulate -> per-sample weights
// grid = NB blocks, 256 threads. ~microseconds.
// =====================================================================
__global__ void prep_weights(const float* __restrict__ style,
                             const float* __restrict__ bank,
                             const float* __restrict__ aff_w,
                             const float* __restrict__ aff_b,
                             const float* __restrict__ sel_w,
                             const float* __restrict__ sel_b) {
    int b = blockIdx.x, tid = threadIdx.x;
    __shared__ float sh_alpha[NBANK];
    __shared__ float sh_s[CIN];
    __shared__ float sh_logit[NBANK];
    const float* st = style + b * MOD;

    if (tid < NBANK) {
        float l = sel_b[tid];
        #pragma unroll 4
        for (int m = 0; m < MOD; m++) l += st[m] * sel_w[tid * MOD + m];
        sh_logit[tid] = l;
    }
    if (tid < CIN) {
        float s = aff_b[tid];
        #pragma unroll 4
        for (int m = 0; m < MOD; m++) s += st[m] * aff_w[tid * MOD + m];
        sh_s[tid] = s;
    }
    __syncthreads();
    if (tid == 0) {
        float m = sh_logit[0];
        for (int n = 1; n < NBANK; n++) m = fmaxf(m, sh_logit[n]);
        float e[NBANK], sum = 0.f;
        for (int n = 0; n < NBANK; n++) { e[n] = expf(sh_logit[n] - m); sum += e[n]; }
        for (int n = 0; n < NBANK; n++) sh_alpha[n] = e[n] / sum;
    }
    __syncthreads();
    float a0 = sh_alpha[0], a1 = sh_alpha[1], a2 = sh_alpha[2], a3 = sh_alpha[3];

    int o = tid >> 3, lane = tid & 7;       // 32 o-groups x 8 lanes
    const int BSTR = COUT * CIN * 27;       // bank stride per n
    float ssq = 0.f;
    for (int j = 0; j < 216; j++) {         // 1728 / 8
        int flat = j * 8 + lane;
        int i = flat / 27, k = flat - i * 27;
        int bi = (o * CIN + i) * 27 + k;
        float wv = a0 * bank[bi] + a1 * bank[bi + BSTR]
                 + a2 * bank[bi + 2 * BSTR] + a3 * bank[bi + 3 * BSTR];
        wv *= sh_s[i];
        g_w[((b * CIN + i) * 27 + k) * COUT + o] = wv;
        ssq += wv * wv;
    }
    // reduce across 8 lanes of the o-group
    for (int off = 4; off; off >>= 1) ssq += __shfl_down_sync(0xffffffffu, ssq, off, 8);
    float demod = rsqrtf(__shfl_sync(0xffffffffu, ssq, 0, 8) + EPSV);
    for (int j = 0; j < 216; j++) {
        int flat = j * 8 + lane;
        int i = flat / 27, k = flat - i * 27;
        int gi = ((b * CIN + i) * 27 + k) * COUT + o;
        g_w[gi] *= demod;                   // same-thread RAW, no sync needed
    }
}

// =====================================================================
// Kernel 2: 3D conv, pad=1, per-sample weights. Packed f32x2 FMAs.
// tile (TZ=2, TY=4, TX=32) -> 256 threads, each thread: 1 voxel x 32 ch.
// grid = (16 z-tiles * 8 y-tiles, NB)
// =====================================================================
#define TZ 2
#define TY 4
#define TX 32
#define HZ (TZ + 2)
#define HY (TY + 2)
#define HX (TX + 2)

__global__ void __launch_bounds__(256, 3)
conv3d_mod(const float* __restrict__ x) {
    __shared__ __align__(16) float s_w[27 * COUT];       // [k][o]
    __shared__ float s_x[HZ * HY * HX];                  // 4*6*34 = 816

    int b    = blockIdx.y;
    int tile = blockIdx.x;
    int y0 = (tile & 7) * TY;
    int z0 = (tile >> 3) * TZ;
    int tx = threadIdx.x;            // 0..31
    int ty = threadIdx.y & 3;
    int tz = threadIdx.y >> 2;
    int tid = threadIdx.y * 32 + tx;

    unsigned long long acc[16];      // 32 channels as 16 f32x2 pairs
    #pragma unroll
    for (int p = 0; p < 16; p++) acc[p] = 0ull;

    const int xbase = tz * (HY * HX) + ty * HX + tx;

    for (int ci = 0; ci < CIN; ci++) {
        __syncthreads();
        // weights: 864 contiguous floats
        const float* wg = g_w + (b * CIN + ci) * 27 * COUT;
        for (int e = tid; e < 27 * COUT; e += 256) s_w[e] = wg[e];
        // x halo tile with zero padding
        const float* xg = x + (b * CIN + ci) * (DSZ * DSZ * DSZ);
        for (int e = tid; e < HZ * HY * HX; e += 256) {
            int lz = e / (HY * HX); int r = e - lz * (HY * HX);
            int ly = r / HX;        int lx = r - ly * HX;
            int gz = z0 + lz - 1, gy = y0 + ly - 1, gx = lx - 1;
            float v = 0.f;
            if ((unsigned)gz < DSZ && (unsigned)gy < DSZ && (unsigned)gx < DSZ)
                v = xg[(gz * DSZ + gy) * DSZ + gx];
            s_x[e] = v;
        }
        __syncthreads();

        #pragma unroll
        for (int kz = 0; kz < 3; kz++)
        #pragma unroll
        for (int ky = 0; ky < 3; ky++)
        #pragma unroll
        for (int kx = 0; kx < 3; kx++) {
            int k = (kz * 3 + ky) * 3 + kx;
            float xv = s_x[xbase + kz * (HY * HX) + ky * HX + kx];
            unsigned xi = __float_as_uint(xv);
            unsigned long long xx;
            asm("mov.b64 %0, {%1, %2};" : "=l"(xx) : "r"(xi), "r"(xi));
            const ulonglong2* wp = reinterpret_cast<const ulonglong2*>(s_w + k * COUT);
            #pragma unroll
            for (int p = 0; p < 8; p++) {
                ulonglong2 w2 = wp[p];
                asm("fma.rn.f32x2 %0, %1, %2, %0;" : "+l"(acc[2*p])   : "l"(xx), "l"(w2.x));
                asm("fma.rn.f32x2 %0, %1, %2, %0;" : "+l"(acc[2*p+1]) : "l"(xx), "l"(w2.y));
            }
        }
    }

    int z = z0 + tz, yy = y0 + ty;
    float* yo = g_ys + (b * COUT * DSZ + z) * (DSZ * DSZ) + yy * DSZ + tx;
    #pragma unroll
    for (int p = 0; p < 16; p++) {
        unsigned lo, hi;
        asm("mov.b64 {%0, %1}, %2;" : "=r"(lo), "=r"(hi) : "l"(acc[p]));
        yo[(2 * p)     * (DSZ * DSZ * DSZ)] = __uint_as_float(lo);
        yo[(2 * p + 1) * (DSZ * DSZ * DSZ)] = __uint_as_float(hi);
    }
}

// =====================================================================
// Kernel 3: trilinear 2x upsample (align_corners=False) + 1x1x1 vox head.
// One thread per output voxel position, loops 32 channels.
// =====================================================================
__global__ void upsample_vox(const float* __restrict__ vox_w,
                             const float* __restrict__ vox_b,
                             float* __restrict__ out) {
    int idx = blockIdx.x * blockDim.x + threadIdx.x;      // NB*64^3 threads
    int X = idx & 63, Y = (idx >> 6) & 63, Z = (idx >> 12) & 63, b = idx >> 18;

    float sx = fmaxf(0.5f * X - 0.25f, 0.f);
    float sy = fmaxf(0.5f * Y - 0.25f, 0.f);
    float sz = fmaxf(0.5f * Z - 0.25f, 0.f);
    int x0 = (int)sx, y0 = (int)sy, z0 = (int)sz;
    float wx = sx - x0, wy = sy - y0, wz = sz - z0;
    int x1 = min(x0 + 1, 31), y1 = min(y0 + 1, 31), z1 = min(z0 + 1, 31);

    int o00 = (z0 * 32 + y0) * 32, o01 = (z0 * 32 + y1) * 32;
    int o10 = (z1 * 32 + y0) * 32, o11 = (z1 * 32 + y1) * 32;
    const float* base = g_ys + b * COUT * (DSZ * DSZ * DSZ);

    int sp = (Z << 12) + (Y << 6) + X;
    float accv = vox_b[0];
    #pragma unroll 4
    for (int o = 0; o < COUT; o++) {
        const float* p = base + o * (DSZ * DSZ * DSZ);
        float v000 = p[o00 + x0], v001 = p[o00 + x1];
        float v010 = p[o01 + x0], v011 = p[o01 + x1];
        float v100 = p[o10 + x0], v101 = p[o10 + x1];
        float v110 = p[o11 + x0], v111 = p[o11 + x1];
        float a = v000 + wx * (v001 - v000);
        float c = v010 + wx * (v011 - v010);
        float e = v100 + wx * (v101 - v100);
        float f = v110 + wx * (v111 - v110);
        float g = a + wy * (c - a);
        float h = e + wy * (f - e);
        float val = g + wz * (h - g);
        out[((b * COUT + o) << 18) + sp] = val;          // y output
        accv += vox_w[o] * val;
    }
    out[((NB * COUT) << 18) + (b << 18) + sp] = accv;    // out output (after y block)
}

// =====================================================================
extern "C" void kernel_launch(void* const* d_in, const int* in_sizes, int n_in,
                              void* d_out, int out_size) {
    const float* x      = (const float*)d_in[0];
    const float* style  = (const float*)d_in[1];
    const float* bank   = (const float*)d_in[2];
    const float* aff_w  = (const float*)d_in[3];
    const float* aff_b  = (const float*)d_in[4];
    const float* sel_w  = (const float*)d_in[5];
    const float* sel_b  = (const float*)d_in[6];
    const float* vox_w  = (const float*)d_in[7];
    const float* vox_b  = (const float*)d_in[8];
    float* out = (float*)d_out;

    prep_weights<<<NB, 256>>>(style, bank, aff_w, aff_b, sel_w, sel_b);
    conv3d_mod<<<dim3(128, NB), dim3(32, 8)>>>(x);
    upsample_vox<<<(NB * 64 * 64 * 64) / 256, 256>>>(vox_w, vox_b, out);
}

// round 11
// speedup vs baseline: 1.0423x; 1.0423x over previous
#include <cuda_runtime.h>

#define NB   4      // batch
#define CIN  64
#define COUT 32
#define NBANK 4
#define MOD  128
#define DSZ  32
#define EPSV 1e-8f

// -------- scratch (static device globals; no allocation allowed) --------
__device__ float g_w[NB * CIN * 27 * COUT];                 // [b][ci][k][o]  (o contiguous)
__device__ float g_ys[NB * COUT * DSZ * DSZ * DSZ];         // [b][o][z][y][x]  16 MB

// =====================================================================
// Kernel 1: bank select + modulate + demodulate -> per-sample weights
// grid = NB blocks, 256 threads. ~microseconds.
// =====================================================================
__global__ void prep_weights(const float* __restrict__ style,
                             const float* __restrict__ bank,
                             const float* __restrict__ aff_w,
                             const float* __restrict__ aff_b,
                             const float* __restrict__ sel_w,
                             const float* __restrict__ sel_b) {
    int b = blockIdx.x, tid = threadIdx.x;
    __shared__ float sh_alpha[NBANK];
    __shared__ float sh_s[CIN];
    __shared__ float sh_logit[NBANK];
    const float* st = style + b * MOD;

    if (tid < NBANK) {
        float l = sel_b[tid];
        #pragma unroll 4
        for (int m = 0; m < MOD; m++) l += st[m] * sel_w[tid * MOD + m];
        sh_logit[tid] = l;
    }
    if (tid < CIN) {
        float s = aff_b[tid];
        #pragma unroll 4
        for (int m = 0; m < MOD; m++) s += st[m] * aff_w[tid * MOD + m];
        sh_s[tid] = s;
    }
    __syncthreads();
    if (tid == 0) {
        float m = sh_logit[0];
        for (int n = 1; n < NBANK; n++) m = fmaxf(m, sh_logit[n]);
        float e[NBANK], sum = 0.f;
        for (int n = 0; n < NBANK; n++) { e[n] = expf(sh_logit[n] - m); sum += e[n]; }
        for (int n = 0; n < NBANK; n++) sh_alpha[n] = e[n] / sum;
    }
    __syncthreads();
    float a0 = sh_alpha[0], a1 = sh_alpha[1], a2 = sh_alpha[2], a3 = sh_alpha[3];

    int o = tid >> 3, lane = tid & 7;       // 32 o-groups x 8 lanes
    const int BSTR = COUT * CIN * 27;       // bank stride per n
    float ssq = 0.f;
    for (int j = 0; j < 216; j++) {         // 1728 / 8
        int flat = j * 8 + lane;
        int i = flat / 27, k = flat - i * 27;
        int bi = (o * CIN + i) * 27 + k;
        float wv = a0 * bank[bi] + a1 * bank[bi + BSTR]
                 + a2 * bank[bi + 2 * BSTR] + a3 * bank[bi + 3 * BSTR];
        wv *= sh_s[i];
        g_w[((b * CIN + i) * 27 + k) * COUT + o] = wv;
        ssq += wv * wv;
    }
    // reduce across 8 lanes of the o-group
    for (int off = 4; off; off >>= 1) ssq += __shfl_down_sync(0xffffffffu, ssq, off, 8);
    float demod = rsqrtf(__shfl_sync(0xffffffffu, ssq, 0, 8) + EPSV);
    for (int j = 0; j < 216; j++) {
        int flat = j * 8 + lane;
        int i = flat / 27, k = flat - i * 27;
        int gi = ((b * CIN + i) * 27 + k) * COUT + o;
        g_w[gi] *= demod;                   // same-thread RAW, no sync needed
    }
}

// =====================================================================
// Kernel 2: 3D conv, pad=1, per-sample weights. Packed f32x2 FMAs.
// tile (TZ=2, TY=4, TX=32) -> 256 threads, each thread: 1 voxel x 32 ch.
// grid = (16 z-tiles * 8 y-tiles, NB)
// =====================================================================
#define TZ 2
#define TY 4
#define TX 32
#define HZ (TZ + 2)
#define HY (TY + 2)
#define HX (TX + 2)

__global__ void __launch_bounds__(256, 3)
conv3d_mod(const float* __restrict__ x) {
    __shared__ __align__(16) float s_w[27 * COUT];       // [k][o]
    __shared__ float s_x[HZ * HY * HX];                  // 4*6*34 = 816

    int b    = blockIdx.y;
    int tile = blockIdx.x;
    int y0 = (tile & 7) * TY;
    int z0 = (tile >> 3) * TZ;
    int tx = threadIdx.x;            // 0..31
    int ty = threadIdx.y & 3;
    int tz = threadIdx.y >> 2;
    int tid = threadIdx.y * 32 + tx;

    unsigned long long acc[16];      // 32 channels as 16 f32x2 pairs
    #pragma unroll
    for (int p = 0; p < 16; p++) acc[p] = 0ull;

    const int xbase = tz * (HY * HX) + ty * HX + tx;

    for (int ci = 0; ci < CIN; ci++) {
        __syncthreads();
        // weights: 864 contiguous floats
        const float* wg = g_w + (b * CIN + ci) * 27 * COUT;
        for (int e = tid; e < 27 * COUT; e += 256) s_w[e] = wg[e];
        // x halo tile with zero padding
        const float* xg = x + (b * CIN + ci) * (DSZ * DSZ * DSZ);
        for (int e = tid; e < HZ * HY * HX; e += 256) {
            int lz = e / (HY * HX); int r = e - lz * (HY * HX);
            int ly = r / HX;        int lx = r - ly * HX;
            int gz = z0 + lz - 1, gy = y0 + ly - 1, gx = lx - 1;
            float v = 0.f;
            if ((unsigned)gz < DSZ && (unsigned)gy < DSZ && (unsigned)gx < DSZ)
                v = xg[(gz * DSZ + gy) * DSZ + gx];
            s_x[e] = v;
        }
        __syncthreads();

        #pragma unroll
        for (int kz = 0; kz < 3; kz++)
        #pragma unroll
        for (int ky = 0; ky < 3; ky++)
        #pragma unroll
        for (int kx = 0; kx < 3; kx++) {
            int k = (kz * 3 + ky) * 3 + kx;
            float xv = s_x[xbase + kz * (HY * HX) + ky * HX + kx];
            unsigned xi = __float_as_uint(xv);
            unsigned long long xx;
            asm("mov.b64 %0, {%1, %2};" : "=l"(xx) : "r"(xi), "r"(xi));
            const ulonglong2* wp = reinterpret_cast<const ulonglong2*>(s_w + k * COUT);
            #pragma unroll
            for (int p = 0; p < 8; p++) {
                ulonglong2 w2 = wp[p];
                asm("fma.rn.f32x2 %0, %1, %2, %0;" : "+l"(acc[2*p])   : "l"(xx), "l"(w2.x));
                asm("fma.rn.f32x2 %0, %1, %2, %0;" : "+l"(acc[2*p+1]) : "l"(xx), "l"(w2.y));
            }
        }
    }

    int z = z0 + tz, yy = y0 + ty;
    float* yo = g_ys + (b * COUT * DSZ + z) * (DSZ * DSZ) + yy * DSZ + tx;
    #pragma unroll
    for (int p = 0; p < 16; p++) {
        unsigned lo, hi;
        asm("mov.b64 {%0, %1}, %2;" : "=r"(lo), "=r"(hi) : "l"(acc[p]));
        yo[(2 * p)     * (DSZ * DSZ * DSZ)] = __uint_as_float(lo);
        yo[(2 * p + 1) * (DSZ * DSZ * DSZ)] = __uint_as_float(hi);
    }
}

// =====================================================================
// Kernel 3: trilinear 2x upsample (align_corners=False) + 1x1x1 vox head.
// One thread per output voxel position, loops 32 channels.
// =====================================================================
__global__ void upsample_vox(const float* __restrict__ vox_w,
                             const float* __restrict__ vox_b,
                             float* __restrict__ out) {
    int idx = blockIdx.x * blockDim.x + threadIdx.x;      // NB*64^3 threads
    int X = idx & 63, Y = (idx >> 6) & 63, Z = (idx >> 12) & 63, b = idx >> 18;

    float sx = fmaxf(0.5f * X - 0.25f, 0.f);
    float sy = fmaxf(0.5f * Y - 0.25f, 0.f);
    float sz = fmaxf(0.5f * Z - 0.25f, 0.f);
    int x0 = (int)sx, y0 = (int)sy, z0 = (int)sz;
    float wx = sx - x0, wy = sy - y0, wz = sz - z0;
    int x1 = min(x0 + 1, 31), y1 = min(y0 + 1, 31), z1 = min(z0 + 1, 31);

    int o00 = (z0 * 32 + y0) * 32, o01 = (z0 * 32 + y1) * 32;
    int o10 = (z1 * 32 + y0) * 32, o11 = (z1 * 32 + y1) * 32;
    const float* base = g_ys + b * COUT * (DSZ * DSZ * DSZ);

    int sp = (Z << 12) + (Y << 6) + X;
    float accv = vox_b[0];
    #pragma unroll 4
    for (int o = 0; o < COUT; o++) {
        const float* p = base + o * (DSZ * DSZ * DSZ);
        float v000 = p[o00 + x0], v001 = p[o00 + x1];
        float v010 = p[o01 + x0], v011 = p[o01 + x1];
        float v100 = p[o10 + x0], v101 = p[o10 + x1];
        float v110 = p[o11 + x0], v111 = p[o11 + x1];
        float a = v000 + wx * (v001 - v000);
        float c = v010 + wx * (v011 - v010);
        float e = v100 + wx * (v101 - v100);
        float f = v110 + wx * (v111 - v110);
        float g = a + wy * (c - a);
        float h = e + wy * (f - e);
        float val = g + wz * (h - g);
        out[((b * COUT + o) << 18) + sp] = val;          // y output
        accv += vox_w[o] * val;
    }
    out[((NB * COUT) << 18) + (b << 18) + sp] = accv;    // out output (after y block)
}

// =====================================================================
extern "C" void kernel_launch(void* const* d_in, const int* in_sizes, int n_in,
                              void* d_out, int out_size) {
    const float* x      = (const float*)d_in[0];
    const float* style  = (const float*)d_in[1];
    const float* bank   = (const float*)d_in[2];
    const float* aff_w  = (const float*)d_in[3];
    const float* aff_b  = (const float*)d_in[4];
    const float* sel_w  = (const float*)d_in[5];
    const float* sel_b  = (const float*)d_in[6];
    const float* vox_w  = (const float*)d_in[7];
    const float* vox_b  = (const float*)d_in[8];
    float* out = (float*)d_out;

    prep_weights<<<NB, 256>>>(style, bank, aff_w, aff_b, sel_w, sel_b);
    conv3d_mod<<<dim3(128, NB), dim3(32, 8)>>>(x);
    upsample_vox<<<(NB * 64 * 64 * 64) / 256, 256>>>(vox_w, vox_b, out);
}

// round 12
// speedup vs baseline: 1.7515x; 1.6803x over previous
#include <cuda_runtime.h>

#define NB    4
#define CIN   64
#define COUT  32
#define NBANK 4
#define MOD   128
#define DSZ   32
#define VOL   (DSZ*DSZ*DSZ)
#define EPSV  1e-8f

// -------- scratch (static device globals; no allocation allowed) --------
__device__ float g_w[NB * CIN * 27 * COUT];     // [b][ci][k][o]  (o contiguous)
__device__ float g_ys[NB * COUT * VOL];         // conv output [b][o][z][y][x]
__device__ float g_s[NB * CIN];                 // modulation scales
__device__ float g_alpha[NB * NBANK];           // softmax bank weights

// =====================================================================
// Kernel 1a: style -> (s, alpha). grid=NB, 128 threads. ~2us.
// =====================================================================
__global__ void prep_style(const float* __restrict__ style,
                           const float* __restrict__ aff_w,
                           const float* __restrict__ aff_b,
                           const float* __restrict__ sel_w,
                           const float* __restrict__ sel_b) {
    int b = blockIdx.x, tid = threadIdx.x;
    __shared__ float sh_logit[NBANK];
    const float* st = style + b * MOD;

    if (tid < CIN) {
        float s = aff_b[tid];
        #pragma unroll 8
        for (int m = 0; m < MOD; m++) s += st[m] * aff_w[tid * MOD + m];
        g_s[b * CIN + tid] = s;
    } else if (tid < CIN + NBANK) {
        int n = tid - CIN;
        float l = sel_b[n];
        #pragma unroll 8
        for (int m = 0; m < MOD; m++) l += st[m] * sel_w[n * MOD + m];
        sh_logit[n] = l;
    }
    __syncthreads();
    if (tid == 0) {
        float mx = sh_logit[0];
        for (int n = 1; n < NBANK; n++) mx = fmaxf(mx, sh_logit[n]);
        float e[NBANK], sum = 0.f;
        for (int n = 0; n < NBANK; n++) { e[n] = expf(sh_logit[n] - mx); sum += e[n]; }
        for (int n = 0; n < NBANK; n++) g_alpha[b * NBANK + n] = e[n] / sum;
    }
}

// =====================================================================
// Kernel 1b: blend banks + modulate + demodulate.
// grid = (COUT, NB) = 128 blocks x 256 threads. ~4us.
// =====================================================================
__global__ void blend_weights(const float* __restrict__ bank) {
    int o = blockIdx.x, b = blockIdx.y, tid = threadIdx.x;
    const int BSTR = COUT * CIN * 27;
    float a0 = g_alpha[b * 4 + 0], a1 = g_alpha[b * 4 + 1];
    float a2 = g_alpha[b * 4 + 2], a3 = g_alpha[b * 4 + 3];
    const float* bk = bank + o * CIN * 27;

    float wv[7];
    float ssq = 0.f;
    #pragma unroll
    for (int j = 0; j < 7; j++) {
        int e = j * 256 + tid;
        float w = 0.f;
        if (e < CIN * 27) {
            int i = e / 27;
            w = a0 * bk[e] + a1 * bk[e + BSTR] + a2 * bk[e + 2 * BSTR] + a3 * bk[e + 3 * BSTR];
            w *= g_s[b * CIN + i];
            ssq += w * w;
        }
        wv[j] = w;
    }
    // block reduce
    #pragma unroll
    for (int off = 16; off; off >>= 1) ssq += __shfl_xor_sync(0xffffffffu, ssq, off);
    __shared__ float sh[8];
    __shared__ float sh_demod;
    if ((tid & 31) == 0) sh[tid >> 5] = ssq;
    __syncthreads();
    if (tid < 8) {
        float v = sh[tid];
        #pragma unroll
        for (int off = 4; off; off >>= 1) v += __shfl_xor_sync(0xffu, v, off);
        if (tid == 0) sh_demod = rsqrtf(v + EPSV);
    }
    __syncthreads();
    float demod = sh_demod;
    #pragma unroll
    for (int j = 0; j < 7; j++) {
        int e = j * 256 + tid;
        if (e < CIN * 27) {
            int i = e / 27, k = e - i * 27;
            g_w[((b * CIN + i) * 27 + k) * COUT + o] = wv[j] * demod;
        }
    }
}

// =====================================================================
// Kernel 2: 3D conv, pad=1, per-sample weights.
// Each thread: 2 z-adjacent voxels x 32 channels (packed f32x2 FMAs).
// Tile: TZ=4, TY=2, TX=32 -> 256 voxels / 128 threads.
// grid = (8 z-tiles * 16 y-tiles, NB) = 512 blocks.
// =====================================================================
#define HZ 6
#define HY 4
#define HX 34
#define HYX (HY*HX)      // 136
#define HALO (HZ*HYX)    // 816

__global__ void __launch_bounds__(128, 4)
conv3d_mod(const float* __restrict__ x) {
    __shared__ __align__(16) float s_w[27 * COUT];   // 864
    __shared__ float s_x[HALO];                       // 816

    int b    = blockIdx.y;
    int tile = blockIdx.x;           // 0..127
    int y0 = (tile & 15) * 2;
    int z0 = (tile >> 4) * 4;
    int tx  = threadIdx.x;           // 0..31
    int yid = threadIdx.y;           // 0..3
    int ty  = yid & 1;
    int tzp = yid >> 1;              // z-pair: voxels z0+2*tzp, z0+2*tzp+1
    int tid = yid * 32 + tx;

    unsigned long long acc0[16], acc1[16];
    #pragma unroll
    for (int p = 0; p < 16; p++) { acc0[p] = 0ull; acc1[p] = 0ull; }

    for (int ci = 0; ci < CIN; ci++) {
        __syncthreads();
        // weights: 864 contiguous floats
        const float* wg = g_w + (b * CIN + ci) * 27 * COUT;
        #pragma unroll
        for (int j = 0; j < 7; j++) {
            int e = j * 128 + tid;
            if (e < 27 * COUT) s_w[e] = wg[e];
        }
        // x halo tile with zero padding
        const float* xg = x + (b * CIN + ci) * VOL;
        #pragma unroll
        for (int j = 0; j < 7; j++) {
            int e = j * 128 + tid;
            if (e < HALO) {
                int lz = e / HYX; int r = e - lz * HYX;
                int ly = r / HX;  int lx = r - ly * HX;
                int gz = z0 + lz - 1, gy = y0 + ly - 1, gx = lx - 1;
                float v = 0.f;
                if ((unsigned)gz < DSZ && (unsigned)gy < DSZ && (unsigned)gx < DSZ)
                    v = xg[(gz * DSZ + gy) * DSZ + gx];
                s_x[e] = v;
            }
        }
        __syncthreads();

        #pragma unroll
        for (int ky = 0; ky < 3; ky++)
        #pragma unroll
        for (int kx = 0; kx < 3; kx++) {
            // 4 z-planes cover taps of both voxels in the pair
            unsigned long long xp[4];
            #pragma unroll
            for (int l = 0; l < 4; l++) {
                float xv = s_x[(tzp * 2 + l) * HYX + (ty + ky) * HX + tx + kx];
                unsigned xi = __float_as_uint(xv);
                asm("mov.b64 %0, {%1, %2};" : "=l"(xp[l]) : "r"(xi), "r"(xi));
            }
            #pragma unroll
            for (int kz = 0; kz < 3; kz++) {
                const ulonglong2* wp =
                    reinterpret_cast<const ulonglong2*>(s_w + ((kz * 3 + ky) * 3 + kx) * COUT);
                #pragma unroll
                for (int p = 0; p < 8; p++) {
                    ulonglong2 w2 = wp[p];
                    asm("fma.rn.f32x2 %0, %1, %2, %0;" : "+l"(acc0[2*p])   : "l"(xp[kz]),   "l"(w2.x));
                    asm("fma.rn.f32x2 %0, %1, %2, %0;" : "+l"(acc0[2*p+1]) : "l"(xp[kz]),   "l"(w2.y));
                    asm("fma.rn.f32x2 %0, %1, %2, %0;" : "+l"(acc1[2*p])   : "l"(xp[kz+1]), "l"(w2.x));
                    asm("fma.rn.f32x2 %0, %1, %2, %0;" : "+l"(acc1[2*p+1]) : "l"(xp[kz+1]), "l"(w2.y));
                }
            }
        }
    }

    int z = z0 + tzp * 2, yy = y0 + ty;
    float* yo0 = g_ys + (b * COUT * DSZ + z) * (DSZ * DSZ) + yy * DSZ + tx;
    float* yo1 = yo0 + DSZ * DSZ;
    #pragma unroll
    for (int p = 0; p < 16; p++) {
        unsigned lo, hi;
        asm("mov.b64 {%0, %1}, %2;" : "=r"(lo), "=r"(hi) : "l"(acc0[p]));
        yo0[(2 * p)     * VOL] = __uint_as_float(lo);
        yo0[(2 * p + 1) * VOL] = __uint_as_float(hi);
        asm("mov.b64 {%0, %1}, %2;" : "=r"(lo), "=r"(hi) : "l"(acc1[p]));
        yo1[(2 * p)     * VOL] = __uint_as_float(lo);
        yo1[(2 * p + 1) * VOL] = __uint_as_float(hi);
    }
}

// =====================================================================
// Kernel 3: trilinear 2x upsample + 1x1x1 vox head, by SOURCE cell.
// Each thread: one source voxel -> 2x2x2 output cube, 27-point clamped
// stencil per channel (index clamping makes uniform 0.25/0.75 weights
// exact at boundaries). float2 stores for y.
// =====================================================================
__global__ void __launch_bounds__(256)
upsample_vox(const float* __restrict__ vox_w,
             const float* __restrict__ vox_b,
             float* __restrict__ out) {
    int idx = blockIdx.x * 256 + threadIdx.x;   // NB*32^3 threads
    int t = idx & 31, v = (idx >> 5) & 31, u = (idx >> 10) & 31, b = idx >> 15;

    int xo[3] = { max(t - 1, 0), t, min(t + 1, 31) };
    int yc[3] = { max(v - 1, 0), v, min(v + 1, 31) };
    int zc[3] = { max(u - 1, 0), u, min(u + 1, 31) };
    int ro[9];
    #pragma unroll
    for (int dz = 0; dz < 3; dz++)
        #pragma unroll
        for (int dy = 0; dy < 3; dy++)
            ro[dz * 3 + dy] = (zc[dz] * DSZ + yc[dy]) * DSZ;

    const float* base = g_ys + b * COUT * VOL;
    int sp00 = ((2 * u) << 12) + ((2 * v) << 6) + 2 * t;
    float accv[8] = {0.f, 0.f, 0.f, 0.f, 0.f, 0.f, 0.f, 0.f};

    #pragma unroll 1
    for (int o = 0; o < COUT; o++) {
        const float* p = base + o * VOL;
        float val[3][3][3];
        #pragma unroll
        for (int dz = 0; dz < 3; dz++)
            #pragma unroll
            for (int dy = 0; dy < 3; dy++)
                #pragma unroll
                for (int dx = 0; dx < 3; dx++)
                    val[dz][dy][dx] = p[ro[dz * 3 + dy] + xo[dx]];

        float ax[3][3][2];
        #pragma unroll
        for (int dz = 0; dz < 3; dz++)
            #pragma unroll
            for (int dy = 0; dy < 3; dy++) {
                ax[dz][dy][0] = 0.25f * val[dz][dy][0] + 0.75f * val[dz][dy][1];
                ax[dz][dy][1] = 0.75f * val[dz][dy][1] + 0.25f * val[dz][dy][2];
            }
        float ay[3][2][2];
        #pragma unroll
        for (int dz = 0; dz < 3; dz++)
            #pragma unroll
            for (int q = 0; q < 2; q++) {
                ay[dz][0][q] = 0.25f * ax[dz][0][q] + 0.75f * ax[dz][1][q];
                ay[dz][1][q] = 0.75f * ax[dz][1][q] + 0.25f * ax[dz][2][q];
            }
        float az[2][2][2];
        #pragma unroll
        for (int r = 0; r < 2; r++)
            #pragma unroll
            for (int q = 0; q < 2; q++) {
                az[0][r][q] = 0.25f * ay[0][r][q] + 0.75f * ay[1][r][q];
                az[1][r][q] = 0.75f * ay[1][r][q] + 0.25f * ay[2][r][q];
            }

        float vw = vox_w[o];
        float* yout = out + (((long long)(b * COUT + o)) << 18) + sp00;
        #pragma unroll
        for (int s = 0; s < 2; s++)
            #pragma unroll
            for (int r = 0; r < 2; r++) {
                *reinterpret_cast<float2*>(yout + (s << 12) + (r << 6)) =
                    make_float2(az[s][r][0], az[s][r][1]);
                accv[s * 4 + r * 2 + 0] += vw * az[s][r][0];
                accv[s * 4 + r * 2 + 1] += vw * az[s][r][1];
            }
    }

    float bias = vox_b[0];
    float* oout = out + (((long long)(NB * COUT + b)) << 18) + sp00;
    #pragma unroll
    for (int s = 0; s < 2; s++)
        #pragma unroll
        for (int r = 0; r < 2; r++) {
            *reinterpret_cast<float2*>(oout + (s << 12) + (r << 6)) =
                make_float2(accv[s * 4 + r * 2 + 0] + bias,
                            accv[s * 4 + r * 2 + 1] + bias);
        }
}

// =====================================================================
extern "C" void kernel_launch(void* const* d_in, const int* in_sizes, int n_in,
                              void* d_out, int out_size) {
    const float* x     = (const float*)d_in[0];
    const float* style = (const float*)d_in[1];
    const float* bank  = (const float*)d_in[2];
    const float* aff_w = (const float*)d_in[3];
    const float* aff_b = (const float*)d_in[4];
    const float* sel_w = (const float*)d_in[5];
    const float* sel_b = (const float*)d_in[6];
    const float* vox_w = (const float*)d_in[7];
    const float* vox_b = (const float*)d_in[8];
    float* out = (float*)d_out;

    prep_style<<<NB, 128>>>(style, aff_w, aff_b, sel_w, sel_b);
    blend_weights<<<dim3(COUT, NB), 256>>>(bank);
    conv3d_mod<<<dim3(128, NB), dim3(32, 4)>>>(x);
    upsample_vox<<<(NB * VOL) / 256, 256>>>(vox_w, vox_b, out);
}

// round 13
// speedup vs baseline: 1.7547x; 1.0018x over previous
#include <cuda_runtime.h>

#define NB    4
#define CIN   64
#define COUT  32
#define NBANK 4
#define MOD   128
#define DSZ   32
#define VOL   (DSZ*DSZ*DSZ)
#define EPSV  1e-8f

// -------- scratch (static device globals; no allocation allowed) --------
__device__ float g_w[NB * CIN * 27 * COUT];     // [b][ci][k][o]  (o contiguous)
__device__ float g_ys[NB * COUT * VOL];         // conv output [b][o][z][y][x]
__device__ float g_s[NB * CIN];                 // modulation scales
__device__ float g_alpha[NB * NBANK];           // softmax bank weights

// =====================================================================
// Kernel 1a: style -> (s, alpha). grid=NB, 128 threads. ~2us.
// =====================================================================
__global__ void prep_style(const float* __restrict__ style,
                           const float* __restrict__ aff_w,
                           const float* __restrict__ aff_b,
                           const float* __restrict__ sel_w,
                           const float* __restrict__ sel_b) {
    int b = blockIdx.x, tid = threadIdx.x;
    __shared__ float sh_logit[NBANK];
    const float* st = style + b * MOD;

    if (tid < CIN) {
        float s = aff_b[tid];
        #pragma unroll 8
        for (int m = 0; m < MOD; m++) s += st[m] * aff_w[tid * MOD + m];
        g_s[b * CIN + tid] = s;
    } else if (tid < CIN + NBANK) {
        int n = tid - CIN;
        float l = sel_b[n];
        #pragma unroll 8
        for (int m = 0; m < MOD; m++) l += st[m] * sel_w[n * MOD + m];
        sh_logit[n] = l;
    }
    __syncthreads();
    if (tid == 0) {
        float mx = sh_logit[0];
        for (int n = 1; n < NBANK; n++) mx = fmaxf(mx, sh_logit[n]);
        float e[NBANK], sum = 0.f;
        for (int n = 0; n < NBANK; n++) { e[n] = expf(sh_logit[n] - mx); sum += e[n]; }
        for (int n = 0; n < NBANK; n++) g_alpha[b * NBANK + n] = e[n] / sum;
    }
}

// =====================================================================
// Kernel 1b: blend banks + modulate + demodulate.
// grid = (COUT, NB) = 128 blocks x 256 threads. ~4us.
// =====================================================================
__global__ void blend_weights(const float* __restrict__ bank) {
    int o = blockIdx.x, b = blockIdx.y, tid = threadIdx.x;
    const int BSTR = COUT * CIN * 27;
    float a0 = g_alpha[b * 4 + 0], a1 = g_alpha[b * 4 + 1];
    float a2 = g_alpha[b * 4 + 2], a3 = g_alpha[b * 4 + 3];
    const float* bk = bank + o * CIN * 27;

    float wv[7];
    float ssq = 0.f;
    #pragma unroll
    for (int j = 0; j < 7; j++) {
        int e = j * 256 + tid;
        float w = 0.f;
        if (e < CIN * 27) {
            int i = e / 27;
            w = a0 * bk[e] + a1 * bk[e + BSTR] + a2 * bk[e + 2 * BSTR] + a3 * bk[e + 3 * BSTR];
            w *= g_s[b * CIN + i];
            ssq += w * w;
        }
        wv[j] = w;
    }
    // block reduce
    #pragma unroll
    for (int off = 16; off; off >>= 1) ssq += __shfl_xor_sync(0xffffffffu, ssq, off);
    __shared__ float sh[8];
    __shared__ float sh_demod;
    if ((tid & 31) == 0) sh[tid >> 5] = ssq;
    __syncthreads();
    if (tid < 8) {
        float v = sh[tid];
        #pragma unroll
        for (int off = 4; off; off >>= 1) v += __shfl_xor_sync(0xffu, v, off);
        if (tid == 0) sh_demod = rsqrtf(v + EPSV);
    }
    __syncthreads();
    float demod = sh_demod;
    #pragma unroll
    for (int j = 0; j < 7; j++) {
        int e = j * 256 + tid;
        if (e < CIN * 27) {
            int i = e / 27, k = e - i * 27;
            g_w[((b * CIN + i) * 27 + k) * COUT + o] = wv[j] * demod;
        }
    }
}

// =====================================================================
// Kernel 2: 3D conv, pad=1, per-sample weights.
// Each thread: 2 z-adjacent voxels x 32 channels (packed f32x2 FMAs).
// Tile: TZ=4, TY=2, TX=32 -> 256 voxels / 128 threads.
// grid = (8 z-tiles * 16 y-tiles, NB) = 512 blocks.
// =====================================================================
#define HZ 6
#define HY 4
#define HX 34
#define HYX (HY*HX)      // 136
#define HALO (HZ*HYX)    // 816

__global__ void __launch_bounds__(128, 4)
conv3d_mod(const float* __restrict__ x) {
    __shared__ __align__(16) float s_w[27 * COUT];   // 864
    __shared__ float s_x[HALO];                       // 816

    int b    = blockIdx.y;
    int tile = blockIdx.x;           // 0..127
    int y0 = (tile & 15) * 2;
    int z0 = (tile >> 4) * 4;
    int tx  = threadIdx.x;           // 0..31
    int yid = threadIdx.y;           // 0..3
    int ty  = yid & 1;
    int tzp = yid >> 1;              // z-pair: voxels z0+2*tzp, z0+2*tzp+1
    int tid = yid * 32 + tx;

    unsigned long long acc0[16], acc1[16];
    #pragma unroll
    for (int p = 0; p < 16; p++) { acc0[p] = 0ull; acc1[p] = 0ull; }

    for (int ci = 0; ci < CIN; ci++) {
        __syncthreads();
        // weights: 864 contiguous floats
        const float* wg = g_w + (b * CIN + ci) * 27 * COUT;
        #pragma unroll
        for (int j = 0; j < 7; j++) {
            int e = j * 128 + tid;
            if (e < 27 * COUT) s_w[e] = wg[e];
        }
        // x halo tile with zero padding
        const float* xg = x + (b * CIN + ci) * VOL;
        #pragma unroll
        for (int j = 0; j < 7; j++) {
            int e = j * 128 + tid;
            if (e < HALO) {
                int lz = e / HYX; int r = e - lz * HYX;
                int ly = r / HX;  int lx = r - ly * HX;
                int gz = z0 + lz - 1, gy = y0 + ly - 1, gx = lx - 1;
                float v = 0.f;
                if ((unsigned)gz < DSZ && (unsigned)gy < DSZ && (unsigned)gx < DSZ)
                    v = xg[(gz * DSZ + gy) * DSZ + gx];
                s_x[e] = v;
            }
        }
        __syncthreads();

        #pragma unroll
        for (int ky = 0; ky < 3; ky++)
        #pragma unroll
        for (int kx = 0; kx < 3; kx++) {
            // 4 z-planes cover taps of both voxels in the pair
            unsigned long long xp[4];
            #pragma unroll
            for (int l = 0; l < 4; l++) {
                float xv = s_x[(tzp * 2 + l) * HYX + (ty + ky) * HX + tx + kx];
                unsigned xi = __float_as_uint(xv);
                asm("mov.b64 %0, {%1, %2};" : "=l"(xp[l]) : "r"(xi), "r"(xi));
            }
            #pragma unroll
            for (int kz = 0; kz < 3; kz++) {
                const ulonglong2* wp =
                    reinterpret_cast<const ulonglong2*>(s_w + ((kz * 3 + ky) * 3 + kx) * COUT);
                #pragma unroll
                for (int p = 0; p < 8; p++) {
                    ulonglong2 w2 = wp[p];
                    asm("fma.rn.f32x2 %0, %1, %2, %0;" : "+l"(acc0[2*p])   : "l"(xp[kz]),   "l"(w2.x));
                    asm("fma.rn.f32x2 %0, %1, %2, %0;" : "+l"(acc0[2*p+1]) : "l"(xp[kz]),   "l"(w2.y));
                    asm("fma.rn.f32x2 %0, %1, %2, %0;" : "+l"(acc1[2*p])   : "l"(xp[kz+1]), "l"(w2.x));
                    asm("fma.rn.f32x2 %0, %1, %2, %0;" : "+l"(acc1[2*p+1]) : "l"(xp[kz+1]), "l"(w2.y));
                }
            }
        }
    }

    int z = z0 + tzp * 2, yy = y0 + ty;
    float* yo0 = g_ys + (b * COUT * DSZ + z) * (DSZ * DSZ) + yy * DSZ + tx;
    float* yo1 = yo0 + DSZ * DSZ;
    #pragma unroll
    for (int p = 0; p < 16; p++) {
        unsigned lo, hi;
        asm("mov.b64 {%0, %1}, %2;" : "=r"(lo), "=r"(hi) : "l"(acc0[p]));
        yo0[(2 * p)     * VOL] = __uint_as_float(lo);
        yo0[(2 * p + 1) * VOL] = __uint_as_float(hi);
        asm("mov.b64 {%0, %1}, %2;" : "=r"(lo), "=r"(hi) : "l"(acc1[p]));
        yo1[(2 * p)     * VOL] = __uint_as_float(lo);
        yo1[(2 * p + 1) * VOL] = __uint_as_float(hi);
    }
}

// =====================================================================
// Kernel 3: trilinear 2x upsample + 1x1x1 vox head, by SOURCE cell.
// Each thread: one source voxel -> 2x2x2 output cube, 27-point clamped
// stencil per channel (index clamping makes uniform 0.25/0.75 weights
// exact at boundaries). float2 stores for y.
// =====================================================================
__global__ void __launch_bounds__(256)
upsample_vox(const float* __restrict__ vox_w,
             const float* __restrict__ vox_b,
             float* __restrict__ out) {
    int idx = blockIdx.x * 256 + threadIdx.x;   // NB*32^3 threads
    int t = idx & 31, v = (idx >> 5) & 31, u = (idx >> 10) & 31, b = idx >> 15;

    int xo[3] = { max(t - 1, 0), t, min(t + 1, 31) };
    int yc[3] = { max(v - 1, 0), v, min(v + 1, 31) };
    int zc[3] = { max(u - 1, 0), u, min(u + 1, 31) };
    int ro[9];
    #pragma unroll
    for (int dz = 0; dz < 3; dz++)
        #pragma unroll
        for (int dy = 0; dy < 3; dy++)
            ro[dz * 3 + dy] = (zc[dz] * DSZ + yc[dy]) * DSZ;

    const float* base = g_ys + b * COUT * VOL;
    int sp00 = ((2 * u) << 12) + ((2 * v) << 6) + 2 * t;
    float accv[8] = {0.f, 0.f, 0.f, 0.f, 0.f, 0.f, 0.f, 0.f};

    #pragma unroll 1
    for (int o = 0; o < COUT; o++) {
        const float* p = base + o * VOL;
        float val[3][3][3];
        #pragma unroll
        for (int dz = 0; dz < 3; dz++)
            #pragma unroll
            for (int dy = 0; dy < 3; dy++)
                #pragma unroll
                for (int dx = 0; dx < 3; dx++)
                    val[dz][dy][dx] = p[ro[dz * 3 + dy] + xo[dx]];

        float ax[3][3][2];
        #pragma unroll
        for (int dz = 0; dz < 3; dz++)
            #pragma unroll
            for (int dy = 0; dy < 3; dy++) {
                ax[dz][dy][0] = 0.25f * val[dz][dy][0] + 0.75f * val[dz][dy][1];
                ax[dz][dy][1] = 0.75f * val[dz][dy][1] + 0.25f * val[dz][dy][2];
            }
        float ay[3][2][2];
        #pragma unroll
        for (int dz = 0; dz < 3; dz++)
            #pragma unroll
            for (int q = 0; q < 2; q++) {
                ay[dz][0][q] = 0.25f * ax[dz][0][q] + 0.75f * ax[dz][1][q];
                ay[dz][1][q] = 0.75f * ax[dz][1][q] + 0.25f * ax[dz][2][q];
            }
        float az[2][2][2];
        #pragma unroll
        for (int r = 0; r < 2; r++)
            #pragma unroll
            for (int q = 0; q < 2; q++) {
                az[0][r][q] = 0.25f * ay[0][r][q] + 0.75f * ay[1][r][q];
                az[1][r][q] = 0.75f * ay[1][r][q] + 0.25f * ay[2][r][q];
            }

        float vw = vox_w[o];
        float* yout = out + (((long long)(b * COUT + o)) << 18) + sp00;
        #pragma unroll
        for (int s = 0; s < 2; s++)
            #pragma unroll
            for (int r = 0; r < 2; r++) {
                *reinterpret_cast<float2*>(yout + (s << 12) + (r << 6)) =
                    make_float2(az[s][r][0], az[s][r][1]);
                accv[s * 4 + r * 2 + 0] += vw * az[s][r][0];
                accv[s * 4 + r * 2 + 1] += vw * az[s][r][1];
            }
    }

    float bias = vox_b[0];
    float* oout = out + (((long long)(NB * COUT + b)) << 18) + sp00;
    #pragma unroll
    for (int s = 0; s < 2; s++)
        #pragma unroll
        for (int r = 0; r < 2; r++) {
            *reinterpret_cast<float2*>(oout + (s << 12) + (r << 6)) =
                make_float2(accv[s * 4 + r * 2 + 0] + bias,
                            accv[s * 4 + r * 2 + 1] + bias);
        }
}

// =====================================================================
extern "C" void kernel_launch(void* const* d_in, const int* in_sizes, int n_in,
                              void* d_out, int out_size) {
    const float* x     = (const float*)d_in[0];
    const float* style = (const float*)d_in[1];
    const float* bank  = (const float*)d_in[2];
    const float* aff_w = (const float*)d_in[3];
    const float* aff_b = (const float*)d_in[4];
    const float* sel_w = (const float*)d_in[5];
    const float* sel_b = (const float*)d_in[6];
    const float* vox_w = (const float*)d_in[7];
    const float* vox_b = (const float*)d_in[8];
    float* out = (float*)d_out;

    prep_style<<<NB, 128>>>(style, aff_w, aff_b, sel_w, sel_b);
    blend_weights<<<dim3(COUT, NB), 256>>>(bank);
    conv3d_mod<<<dim3(128, NB), dim3(32, 4)>>>(x);
    upsample_vox<<<(NB * VOL) / 256, 256>>>(vox_w, vox_b, out);
}

// round 14
// speedup vs baseline: 1.7567x; 1.0011x over previous
#include <cuda_runtime.h>

#define NB    4
#define CIN   64
#define COUT  32
#define NBANK 4
#define MOD   128
#define DSZ   32
#define VOL   (DSZ*DSZ*DSZ)
#define EPSV  1e-8f

// -------- scratch (static device globals; no allocation allowed) --------
__device__ float g_w[NB * CIN * 27 * COUT];     // [b][ci][k][o]  (o contiguous)
__device__ float g_ys[NB * COUT * VOL];         // conv output [b][o][z][y][x]
__device__ float g_s[NB * CIN];                 // modulation scales
__device__ float g_alpha[NB * NBANK];           // softmax bank weights

// =====================================================================
// Kernel 1a: style -> (s, alpha). grid=NB, 128 threads. ~2us.
// =====================================================================
__global__ void prep_style(const float* __restrict__ style,
                           const float* __restrict__ aff_w,
                           const float* __restrict__ aff_b,
                           const float* __restrict__ sel_w,
                           const float* __restrict__ sel_b) {
    int b = blockIdx.x, tid = threadIdx.x;
    __shared__ float sh_logit[NBANK];
    const float* st = style + b * MOD;

    if (tid < CIN) {
        float s = aff_b[tid];
        #pragma unroll 8
        for (int m = 0; m < MOD; m++) s += st[m] * aff_w[tid * MOD + m];
        g_s[b * CIN + tid] = s;
    } else if (tid < CIN + NBANK) {
        int n = tid - CIN;
        float l = sel_b[n];
        #pragma unroll 8
        for (int m = 0; m < MOD; m++) l += st[m] * sel_w[n * MOD + m];
        sh_logit[n] = l;
    }
    __syncthreads();
    if (tid == 0) {
        float mx = sh_logit[0];
        for (int n = 1; n < NBANK; n++) mx = fmaxf(mx, sh_logit[n]);
        float e[NBANK], sum = 0.f;
        for (int n = 0; n < NBANK; n++) { e[n] = expf(sh_logit[n] - mx); sum += e[n]; }
        for (int n = 0; n < NBANK; n++) g_alpha[b * NBANK + n] = e[n] / sum;
    }
}

// =====================================================================
// Kernel 1b: blend banks + modulate + demodulate.
// grid = (COUT, NB) = 128 blocks x 256 threads. ~4us.
// =====================================================================
__global__ void blend_weights(const float* __restrict__ bank) {
    int o = blockIdx.x, b = blockIdx.y, tid = threadIdx.x;
    const int BSTR = COUT * CIN * 27;
    float a0 = g_alpha[b * 4 + 0], a1 = g_alpha[b * 4 + 1];
    float a2 = g_alpha[b * 4 + 2], a3 = g_alpha[b * 4 + 3];
    const float* bk = bank + o * CIN * 27;

    float wv[7];
    float ssq = 0.f;
    #pragma unroll
    for (int j = 0; j < 7; j++) {
        int e = j * 256 + tid;
        float w = 0.f;
        if (e < CIN * 27) {
            int i = e / 27;
            w = a0 * bk[e] + a1 * bk[e + BSTR] + a2 * bk[e + 2 * BSTR] + a3 * bk[e + 3 * BSTR];
            w *= g_s[b * CIN + i];
            ssq += w * w;
        }
        wv[j] = w;
    }
    // block reduce
    #pragma unroll
    for (int off = 16; off; off >>= 1) ssq += __shfl_xor_sync(0xffffffffu, ssq, off);
    __shared__ float sh[8];
    __shared__ float sh_demod;
    if ((tid & 31) == 0) sh[tid >> 5] = ssq;
    __syncthreads();
    if (tid < 8) {
        float v = sh[tid];
        #pragma unroll
        for (int off = 4; off; off >>= 1) v += __shfl_xor_sync(0xffu, v, off);
        if (tid == 0) sh_demod = rsqrtf(v + EPSV);
    }
    __syncthreads();
    float demod = sh_demod;
    #pragma unroll
    for (int j = 0; j < 7; j++) {
        int e = j * 256 + tid;
        if (e < CIN * 27) {
            int i = e / 27, k = e - i * 27;
            g_w[((b * CIN + i) * 27 + k) * COUT + o] = wv[j] * demod;
        }
    }
}

// =====================================================================
// Kernel 2: 3D conv, pad=1, per-sample weights.
// Each thread: 2 z-adjacent voxels x 32 channels (packed f32x2 FMAs).
// Tile: TZ=4, TY=2, TX=32 -> 256 voxels / 128 threads.
// grid = (8 z-tiles * 16 y-tiles, NB) = 512 blocks.
// =====================================================================
#define HZ 6
#define HY 4
#define HX 34
#define HYX (HY*HX)      // 136
#define HALO (HZ*HYX)    // 816

__global__ void __launch_bounds__(128, 4)
conv3d_mod(const float* __restrict__ x) {
    __shared__ __align__(16) float s_w[27 * COUT];   // 864
    __shared__ float s_x[HALO];                       // 816

    int b    = blockIdx.y;
    int tile = blockIdx.x;           // 0..127
    int y0 = (tile & 15) * 2;
    int z0 = (tile >> 4) * 4;
    int tx  = threadIdx.x;           // 0..31
    int yid = threadIdx.y;           // 0..3
    int ty  = yid & 1;
    int tzp = yid >> 1;              // z-pair: voxels z0+2*tzp, z0+2*tzp+1
    int tid = yid * 32 + tx;

    unsigned long long acc0[16], acc1[16];
    #pragma unroll
    for (int p = 0; p < 16; p++) { acc0[p] = 0ull; acc1[p] = 0ull; }

    for (int ci = 0; ci < CIN; ci++) {
        __syncthreads();
        // weights: 864 contiguous floats
        const float* wg = g_w + (b * CIN + ci) * 27 * COUT;
        #pragma unroll
        for (int j = 0; j < 7; j++) {
            int e = j * 128 + tid;
            if (e < 27 * COUT) s_w[e] = wg[e];
        }
        // x halo tile with zero padding
        const float* xg = x + (b * CIN + ci) * VOL;
        #pragma unroll
        for (int j = 0; j < 7; j++) {
            int e = j * 128 + tid;
            if (e < HALO) {
                int lz = e / HYX; int r = e - lz * HYX;
                int ly = r / HX;  int lx = r - ly * HX;
                int gz = z0 + lz - 1, gy = y0 + ly - 1, gx = lx - 1;
                float v = 0.f;
                if ((unsigned)gz < DSZ && (unsigned)gy < DSZ && (unsigned)gx < DSZ)
                    v = xg[(gz * DSZ + gy) * DSZ + gx];
                s_x[e] = v;
            }
        }
        __syncthreads();

        #pragma unroll
        for (int ky = 0; ky < 3; ky++)
        #pragma unroll
        for (int kx = 0; kx < 3; kx++) {
            // 4 z-planes cover taps of both voxels in the pair
            unsigned long long xp[4];
            #pragma unroll
            for (int l = 0; l < 4; l++) {
                float xv = s_x[(tzp * 2 + l) * HYX + (ty + ky) * HX + tx + kx];
                unsigned xi = __float_as_uint(xv);
                asm("mov.b64 %0, {%1, %2};" : "=l"(xp[l]) : "r"(xi), "r"(xi));
            }
            #pragma unroll
            for (int kz = 0; kz < 3; kz++) {
                const ulonglong2* wp =
                    reinterpret_cast<const ulonglong2*>(s_w + ((kz * 3 + ky) * 3 + kx) * COUT);
                #pragma unroll
                for (int p = 0; p < 8; p++) {
                    ulonglong2 w2 = wp[p];
                    asm("fma.rn.f32x2 %0, %1, %2, %0;" : "+l"(acc0[2*p])   : "l"(xp[kz]),   "l"(w2.x));
                    asm("fma.rn.f32x2 %0, %1, %2, %0;" : "+l"(acc0[2*p+1]) : "l"(xp[kz]),   "l"(w2.y));
                    asm("fma.rn.f32x2 %0, %1, %2, %0;" : "+l"(acc1[2*p])   : "l"(xp[kz+1]), "l"(w2.x));
                    asm("fma.rn.f32x2 %0, %1, %2, %0;" : "+l"(acc1[2*p+1]) : "l"(xp[kz+1]), "l"(w2.y));
                }
            }
        }
    }

    int z = z0 + tzp * 2, yy = y0 + ty;
    float* yo0 = g_ys + (b * COUT * DSZ + z) * (DSZ * DSZ) + yy * DSZ + tx;
    float* yo1 = yo0 + DSZ * DSZ;
    #pragma unroll
    for (int p = 0; p < 16; p++) {
        unsigned lo, hi;
        asm("mov.b64 {%0, %1}, %2;" : "=r"(lo), "=r"(hi) : "l"(acc0[p]));
        yo0[(2 * p)     * VOL] = __uint_as_float(lo);
        yo0[(2 * p + 1) * VOL] = __uint_as_float(hi);
        asm("mov.b64 {%0, %1}, %2;" : "=r"(lo), "=r"(hi) : "l"(acc1[p]));
        yo1[(2 * p)     * VOL] = __uint_as_float(lo);
        yo1[(2 * p + 1) * VOL] = __uint_as_float(hi);
    }
}

// =====================================================================
// Kernel 3: trilinear 2x upsample + 1x1x1 vox head, by SOURCE cell.
// Each thread: one source voxel -> 2x2x2 output cube, 27-point clamped
// stencil per channel (index clamping makes uniform 0.25/0.75 weights
// exact at boundaries). float2 stores for y.
// =====================================================================
__global__ void __launch_bounds__(256)
upsample_vox(const float* __restrict__ vox_w,
             const float* __restrict__ vox_b,
             float* __restrict__ out) {
    int idx = blockIdx.x * 256 + threadIdx.x;   // NB*32^3 threads
    int t = idx & 31, v = (idx >> 5) & 31, u = (idx >> 10) & 31, b = idx >> 15;

    int xo[3] = { max(t - 1, 0), t, min(t + 1, 31) };
    int yc[3] = { max(v - 1, 0), v, min(v + 1, 31) };
    int zc[3] = { max(u - 1, 0), u, min(u + 1, 31) };
    int ro[9];
    #pragma unroll
    for (int dz = 0; dz < 3; dz++)
        #pragma unroll
        for (int dy = 0; dy < 3; dy++)
            ro[dz * 3 + dy] = (zc[dz] * DSZ + yc[dy]) * DSZ;

    const float* base = g_ys + b * COUT * VOL;
    int sp00 = ((2 * u) << 12) + ((2 * v) << 6) + 2 * t;
    float accv[8] = {0.f, 0.f, 0.f, 0.f, 0.f, 0.f, 0.f, 0.f};

    #pragma unroll 1
    for (int o = 0; o < COUT; o++) {
        const float* p = base + o * VOL;
        float val[3][3][3];
        #pragma unroll
        for (int dz = 0; dz < 3; dz++)
            #pragma unroll
            for (int dy = 0; dy < 3; dy++)
                #pragma unroll
                for (int dx = 0; dx < 3; dx++)
                    val[dz][dy][dx] = p[ro[dz * 3 + dy] + xo[dx]];

        float ax[3][3][2];
        #pragma unroll
        for (int dz = 0; dz < 3; dz++)
            #pragma unroll
            for (int dy = 0; dy < 3; dy++) {
                ax[dz][dy][0] = 0.25f * val[dz][dy][0] + 0.75f * val[dz][dy][1];
                ax[dz][dy][1] = 0.75f * val[dz][dy][1] + 0.25f * val[dz][dy][2];
            }
        float ay[3][2][2];
        #pragma unroll
        for (int dz = 0; dz < 3; dz++)
            #pragma unroll
            for (int q = 0; q < 2; q++) {
                ay[dz][0][q] = 0.25f * ax[dz][0][q] + 0.75f * ax[dz][1][q];
                ay[dz][1][q] = 0.75f * ax[dz][1][q] + 0.25f * ax[dz][2][q];
            }
        float az[2][2][2];
        #pragma unroll
        for (int r = 0; r < 2; r++)
            #pragma unroll
            for (int q = 0; q < 2; q++) {
                az[0][r][q] = 0.25f * ay[0][r][q] + 0.75f * ay[1][r][q];
                az[1][r][q] = 0.75f * ay[1][r][q] + 0.25f * ay[2][r][q];
            }

        float vw = vox_w[o];
        float* yout = out + (((long long)(b * COUT + o)) << 18) + sp00;
        #pragma unroll
        for (int s = 0; s < 2; s++)
            #pragma unroll
            for (int r = 0; r < 2; r++) {
                *reinterpret_cast<float2*>(yout + (s << 12) + (r << 6)) =
                    make_float2(az[s][r][0], az[s][r][1]);
                accv[s * 4 + r * 2 + 0] += vw * az[s][r][0];
                accv[s * 4 + r * 2 + 1] += vw * az[s][r][1];
            }
    }

    float bias = vox_b[0];
    float* oout = out + (((long long)(NB * COUT + b)) << 18) + sp00;
    #pragma unroll
    for (int s = 0; s < 2; s++)
        #pragma unroll
        for (int r = 0; r < 2; r++) {
            *reinterpret_cast<float2*>(oout + (s << 12) + (r << 6)) =
                make_float2(accv[s * 4 + r * 2 + 0] + bias,
                            accv[s * 4 + r * 2 + 1] + bias);
        }
}

// =====================================================================
extern "C" void kernel_launch(void* const* d_in, const int* in_sizes, int n_in,
                              void* d_out, int out_size) {
    const float* x     = (const float*)d_in[0];
    const float* style = (const float*)d_in[1];
    const float* bank  = (const float*)d_in[2];
    const float* aff_w = (const float*)d_in[3];
    const float* aff_b = (const float*)d_in[4];
    const float* sel_w = (const float*)d_in[5];
    const float* sel_b = (const float*)d_in[6];
    const float* vox_w = (const float*)d_in[7];
    const float* vox_b = (const float*)d_in[8];
    float* out = (float*)d_out;

    prep_style<<<NB, 128>>>(style, aff_w, aff_b, sel_w, sel_b);
    blend_weights<<<dim3(COUT, NB), 256>>>(bank);
    conv3d_mod<<<dim3(128, NB), dim3(32, 4)>>>(x);
    upsample_vox<<<(NB * VOL) / 256, 256>>>(vox_w, vox_b, out);
}